// round 16
// baseline (speedup 1.0000x reference)
#include <cuda_runtime.h>
#include <cuda_fp16.h>
#include <cstdint>

#define N_NODES 100000
#define N_EDGES 3200000
#define D 256
#define BM 128            // block M
#define BN 128            // block N (grid.y = 2)
#define BK 32             // K per stage
#define NIT (D / BK)      // 8 iterations
#define NSTG 3            // pipeline stages

typedef unsigned short ushortT;

__device__ float g_deg[N_NODES];                // 1 + out-degree (written absolutely)
__device__ __align__(16) ushortT g_Wh[D * D];   // fp16 W

// ---- stage layout (32KB per stage, 3 stages = 96KB) ----
#define OFF_AH 0           // 128 rows x 32 fp16 (64B rows, swizzled)   8KB
#define OFF_BH 8192        // 128 rows x 32 fp16                        8KB
#define OFF_XF 16384       // 128 rows x 32 f32 (128B rows, swizzled)  16KB
#define STG_BYTES 32768
#define SMEM_TOTAL (NSTG * STG_BYTES)    // 96KB

// ---------------------------------------------------------------------------
__device__ __forceinline__ uint32_t smem_u32(const void* p) {
    uint32_t a;
    asm("{ .reg .u64 t; cvta.to.shared.u64 t, %1; cvt.u32.u64 %0, t; }" : "=r"(a) : "l"(p));
    return a;
}

#define CP_ASYNC16(dst, src) \
    asm volatile("cp.async.cg.shared.global [%0], [%1], 16;" :: "r"(dst), "l"(src) : "memory")
#define CP_COMMIT() asm volatile("cp.async.commit_group;" ::: "memory")
#define CP_WAIT0()  asm volatile("cp.async.wait_group 0;" ::: "memory")
#define CP_WAIT1()  asm volatile("cp.async.wait_group 1;" ::: "memory")

#define LDSM4(d, addr)                                                         \
    asm volatile("ldmatrix.sync.aligned.m8n8.x4.shared.b16 {%0,%1,%2,%3}, [%4];" \
                 : "=r"((d)[0]), "=r"((d)[1]), "=r"((d)[2]), "=r"((d)[3])      \
                 : "r"(addr))

#define MMA(c, a, b0, b1)                                                      \
    asm volatile("mma.sync.aligned.m16n8k16.row.col.f32.f16.f16.f32 "          \
                 "{%0,%1,%2,%3},{%4,%5,%6,%7},{%8,%9},{%0,%1,%2,%3};"          \
                 : "+f"((c)[0]), "+f"((c)[1]), "+f"((c)[2]), "+f"((c)[3])      \
                 : "r"((a)[0]), "r"((a)[1]), "r"((a)[2]), "r"((a)[3]),         \
                   "r"(b0), "r"(b1))

// ---------------------------------------------------------------------------
// Single fused prep (no init pass; deg written absolutely):
//  - src = edge_index[0] sorted ascending (np.unique construction).
//  - Thread at each run end finds the run START via lower_bound(src, s)
//    (~22 L2-resident steps; only ~100k of 3.2M threads take this path) and
//    writes deg[s] = 1 + runlen = 2 + (t - start).
//  - Gap nodes (no out-edges, rare) get deg = 1: run-end thread fills
//    (s, next_value); thread 0 fills [0, src[0]).
//  - Threads < D*D also convert W f32 -> fp16.
// ---------------------------------------------------------------------------
__global__ void prep_kernel(const int* __restrict__ src,
                            const float* __restrict__ W) {
    int t = blockIdx.x * blockDim.x + threadIdx.x;

    if (t < D * D)
        g_Wh[t] = __half_as_ushort(__float2half_rn(W[t]));

    if (t >= N_EDGES) return;
    int s = src[t];

    if (t == 0)
        for (int g = 0; g < s; g++) g_deg[g] = 1.0f;      // head gap

    int nxt = (t == N_EDGES - 1) ? N_NODES : src[t + 1];
    if (nxt != s) {                                        // run end
        int lo = 0, hi = t;                                // lower_bound(src, s)
        while (lo < hi) {
            int mid = (lo + hi) >> 1;
            if (src[mid] < s) lo = mid + 1; else hi = mid;
        }
        g_deg[s] = 2.0f + (float)(t - lo);                 // 1 + runlen
        for (int g = s + 1; g < nxt; g++) g_deg[g] = 1.0f; // middle/tail gaps
    }
}

// ---------------------------------------------------------------------------
// fp16 tensor GEMM + GraphConv epilogue (Round-12 measured-best config).
//   out[m][n] = deg[m] * sum_k X[m][k]*W[n][k] + b[n]
// Block 128x128, 256 thr (8 warps, 2M x 4N), warp tile 64x32, BK=32,
// 3-stage cp.async pipeline, single fp16 term (f32 accumulate).
// One __syncthreads per iteration; X f32->fp16 conversion thread-private.
// Warps 0-3 process kk halves (0,1); warps 4-7 (1,0).
// ---------------------------------------------------------------------------
__global__ __launch_bounds__(256, 2)
void gemm_f16_kernel(const float* __restrict__ X,
                     const float* __restrict__ bias,
                     float* __restrict__ out) {
    extern __shared__ __align__(1024) char smem[];
    const uint32_t sb = smem_u32(smem);

    const int tid  = threadIdx.x;
    const int lane = tid & 31;
    const int wid  = tid >> 5;
    const int wm   = wid & 1;        // 0..1  M (64 rows each)
    const int wn   = wid >> 1;       // 0..3  N (32 cols each)
    const int m0   = blockIdx.x * BM;
    const int n0   = blockIdx.y * BN;
    const int h0   = (wid >> 2) & 1; // kk-half order stagger per warp group
    const int h1   = h0 ^ 1;

    // copy roles
    const int xrow  = tid >> 1;                       // 0..127
    const int xgrow = min(m0 + xrow, N_NODES - 1);    // clamp OOB rows (masked at store)
    const int hsel  = tid & 1;                        // which 16-col half of BK

    auto issue_stage = [&](int s, int k0) {
        const uint32_t st = sb + s * STG_BYTES;
        // X f32: 128 x 32 f32, 128B rows, 8 chunks, chunk' = chunk ^ (row&7)
        const float* xs = X + (size_t)xgrow * D + k0 + hsel * 16;
        const uint32_t xd = st + OFF_XF + xrow * 128;
        #pragma unroll
        for (int q = 0; q < 4; q++) {
            int ch = hsel * 4 + q;
            CP_ASYNC16(xd + ((ch ^ (xrow & 7)) << 4), xs + q * 4);
        }
        // W fp16: 128 x 32 halves, 64B rows, 4 chunks, chunk' = ch ^ ((row>>1)&3)
        const ushortT* wh = g_Wh + (size_t)(n0 + xrow) * D + k0 + hsel * 16;
        #pragma unroll
        for (int q = 0; q < 2; q++) {
            int ch = hsel * 2 + q;
            uint32_t off = (uint32_t)(xrow * 64 + ((ch ^ ((xrow >> 1) & 3)) << 4));
            CP_ASYNC16(st + OFF_BH + off, wh + q * 8);
        }
    };

    auto convert_x = [&](int s) {
        char* stc = smem + s * STG_BYTES;
        #pragma unroll
        for (int h = 0; h < 2; h++) {
            int c0 = hsel * 4 + h * 2;
            float4 f0 = *reinterpret_cast<const float4*>(
                stc + OFF_XF + xrow * 128 + ((c0 ^ (xrow & 7)) << 4));
            float4 f1 = *reinterpret_cast<const float4*>(
                stc + OFF_XF + xrow * 128 + (((c0 + 1) ^ (xrow & 7)) << 4));
            union { __half2 h2[4]; uint4 v; } ph;
            ph.h2[0] = __floats2half2_rn(f0.x, f0.y);
            ph.h2[1] = __floats2half2_rn(f0.z, f0.w);
            ph.h2[2] = __floats2half2_rn(f1.x, f1.y);
            ph.h2[3] = __floats2half2_rn(f1.z, f1.w);
            int ca = hsel * 2 + h;
            uint32_t ao = (uint32_t)(xrow * 64 + ((ca ^ ((xrow >> 1) & 3)) << 4));
            *reinterpret_cast<uint4*>(stc + OFF_AH + ao) = ph.v;
        }
    };

    float acc[4][4][4];
    #pragma unroll
    for (int i = 0; i < 4; i++)
        #pragma unroll
        for (int j = 0; j < 4; j++)
            #pragma unroll
            for (int e = 0; e < 4; e++) acc[i][j][e] = 0.0f;

    auto compute_half = [&](uint32_t stb, int kk) {
        uint32_t Af[4][4], Bh[2][4];
        #pragma unroll
        for (int i = 0; i < 4; i++) {
            int rA = wm * 64 + i * 16 + (lane & 15);
            uint32_t off = (uint32_t)(rA * 64 +
                (((kk * 2 + (lane >> 4)) ^ ((rA >> 1) & 3)) << 4));
            LDSM4(Af[i], stb + OFF_AH + off);
        }
        const int rB0 = wn * 32 + (lane & 7) + ((lane >> 4) << 3);
        #pragma unroll
        for (int jp = 0; jp < 2; jp++) {
            int rB = rB0 + jp * 16;
            uint32_t off = (uint32_t)(rB * 64 +
                (((kk * 2 + ((lane >> 3) & 1)) ^ ((rB >> 1) & 3)) << 4));
            LDSM4(Bh[jp], stb + OFF_BH + off);
        }
        #pragma unroll
        for (int i = 0; i < 4; i++)
            #pragma unroll
            for (int jp = 0; jp < 2; jp++) {
                MMA(acc[i][2 * jp],     Af[i], Bh[jp][0], Bh[jp][1]);
                MMA(acc[i][2 * jp + 1], Af[i], Bh[jp][2], Bh[jp][3]);
            }
    };

    // prologue: stages 0,1 in flight; convert 0; publish
    issue_stage(0, 0);        CP_COMMIT();
    issue_stage(1, BK);       CP_COMMIT();
    CP_WAIT1();               // stage 0 arrived (stage 1 may still fly)
    convert_x(0);
    __syncthreads();

    #pragma unroll
    for (int it = 0; it < NIT; ++it) {
        const int s = it % NSTG;
        const uint32_t stb = sb + s * STG_BYTES;

        if (it + 2 < NIT) { issue_stage((it + 2) % NSTG, (it + 2) * BK); CP_COMMIT(); }

        compute_half(stb, h0);

        if (it + 1 < NIT) {          // own-thread copy wait + private convert
            if (it + 2 < NIT) CP_WAIT1(); else CP_WAIT0();
            convert_x((it + 1) % NSTG);
        }

        compute_half(stb, h1);

        if (it + 1 < NIT) __syncthreads();   // publish stage it+1; retire stage s reads
    }

    // ---- epilogue: out[m][n] = deg[m]*acc + b[n] ----
    float2 bj[4];
    #pragma unroll
    for (int j = 0; j < 4; j++) {
        int col = n0 + wn * 32 + j * 8 + (lane & 3) * 2;
        bj[j].x = bias[col];
        bj[j].y = bias[col + 1];
    }

    #pragma unroll
    for (int i = 0; i < 4; i++) {
        int r0 = m0 + wm * 64 + i * 16 + (lane >> 2);
        #pragma unroll
        for (int h = 0; h < 2; h++) {
            int row = r0 + h * 8;
            if (row < N_NODES) {
                float d = g_deg[row];
                #pragma unroll
                for (int j = 0; j < 4; j++) {
                    int col = n0 + wn * 32 + j * 8 + (lane & 3) * 2;
                    float2 o;
                    o.x = fmaf(d, acc[i][j][2 * h],     bj[j].x);
                    o.y = fmaf(d, acc[i][j][2 * h + 1], bj[j].y);
                    *reinterpret_cast<float2*>(&out[(size_t)row * D + col]) = o;
                }
            }
        }
    }
}

extern "C" void kernel_launch(void* const* d_in, const int* in_sizes, int n_in,
                              void* d_out, int out_size) {
    const float* x  = (const float*)d_in[0];   // [100000, 256] f32
    const int*   ei = (const int*)d_in[1];     // [2, 3200000] i32, row 0 = src (sorted)
    const float* W  = (const float*)d_in[2];   // [256, 256] f32
    const float* b  = (const float*)d_in[3];   // [256] f32
    float* out = (float*)d_out;                // [100000, 256] f32

    prep_kernel<<<(N_EDGES + 255) / 256, 256>>>(ei, W);   // ONE launch: deg + convW

    cudaFuncSetAttribute(gemm_f16_kernel,
                         cudaFuncAttributeMaxDynamicSharedMemorySize, SMEM_TOTAL);
    dim3 grid((N_NODES + BM - 1) / BM, D / BN);           // 782 x 2
    gemm_f16_kernel<<<grid, 256, SMEM_TOTAL>>>(x, b, out);
}

// round 17
// speedup vs baseline: 3.1107x; 3.1107x over previous
#include <cuda_runtime.h>
#include <cuda_fp16.h>
#include <cstdint>

#define N_NODES 100000
#define N_EDGES 3200000
#define D 256
#define BM 128            // block M
#define BN 128            // block N (grid.x = 2 -> siblings adjacent)
#define BK 32             // K per stage
#define NIT (D / BK)      // 8 iterations
#define NSTG 3            // pipeline stages

typedef unsigned short ushortT;

__device__ int g_cnt[N_NODES];                  // out-degree counts
__device__ __align__(16) ushortT g_Wh[D * D];   // fp16 W

// ---- stage layout (32KB per stage, 3 stages = 96KB) ----
#define OFF_AH 0           // 128 rows x 32 fp16 (64B rows, swizzled)   8KB
#define OFF_BH 8192        // 128 rows x 32 fp16                        8KB
#define OFF_XF 16384       // 128 rows x 32 f32 (128B rows, swizzled)  16KB
#define STG_BYTES 32768
#define SMEM_TOTAL (NSTG * STG_BYTES)    // 96KB

// ---------------------------------------------------------------------------
__device__ __forceinline__ uint32_t smem_u32(const void* p) {
    uint32_t a;
    asm("{ .reg .u64 t; cvta.to.shared.u64 t, %1; cvt.u32.u64 %0, t; }" : "=r"(a) : "l"(p));
    return a;
}

#define CP_ASYNC16(dst, src) \
    asm volatile("cp.async.cg.shared.global [%0], [%1], 16;" :: "r"(dst), "l"(src) : "memory")
#define CP_COMMIT() asm volatile("cp.async.commit_group;" ::: "memory")
#define CP_WAIT0()  asm volatile("cp.async.wait_group 0;" ::: "memory")
#define CP_WAIT1()  asm volatile("cp.async.wait_group 1;" ::: "memory")

#define LDSM4(d, addr)                                                         \
    asm volatile("ldmatrix.sync.aligned.m8n8.x4.shared.b16 {%0,%1,%2,%3}, [%4];" \
                 : "=r"((d)[0]), "=r"((d)[1]), "=r"((d)[2]), "=r"((d)[3])      \
                 : "r"(addr))

#define MMA(c, a, b0, b1)                                                      \
    asm volatile("mma.sync.aligned.m16n8k16.row.col.f32.f16.f16.f32 "          \
                 "{%0,%1,%2,%3},{%4,%5,%6,%7},{%8,%9},{%0,%1,%2,%3};"          \
                 : "+f"((c)[0]), "+f"((c)[1]), "+f"((c)[2]), "+f"((c)[3])      \
                 : "r"((a)[0]), "r"((a)[1]), "r"((a)[2]), "r"((a)[3]),         \
                   "r"(b0), "r"(b1))

// ---------------------------------------------------------------------------
// prep1: zero counters (full N_NODES grid) + convert W -> fp16.
// prep2: warp-aggregated degree count over sorted src: ~1-2 atomics/warp.
// (Measured-best prep; Rounds 6 & 16 proved serial/divergent prep is 20x worse.)
// ---------------------------------------------------------------------------
__global__ void prep1_kernel(const float* __restrict__ W) {
    int t = blockIdx.x * blockDim.x + threadIdx.x;
    if (t < N_NODES) g_cnt[t] = 0;
    if (t < D * D)   g_Wh[t] = __half_as_ushort(__float2half_rn(W[t]));
}
__global__ void prep2_kernel(const int* __restrict__ src) {
    int t = blockIdx.x * blockDim.x + threadIdx.x;
    if (t >= N_EDGES) return;
    int s = src[t];
    unsigned mask = __match_any_sync(0xFFFFFFFFu, s);
    int leader = __ffs(mask) - 1;
    if ((threadIdx.x & 31) == leader)
        atomicAdd(&g_cnt[s], __popc(mask));
}

// ---------------------------------------------------------------------------
// fp16 tensor GEMM + GraphConv epilogue (Round-12 config + L2-reuse fixes).
//   out[m][n] = (1 + cnt[m]) * sum_k X[m][k]*W[n][k] + b[n]
// Block 128x128, 256 thr (8 warps, 2M x 4N), warp tile 64x32, BK=32,
// 3-stage cp.async pipeline, single fp16 term, one barrier/iter.
// NEW: grid is (N=2, M=782) so the two N-halves of each M-block are ADJACENT
// in launch order -> co-resident -> the 2nd X read hits L2 (DRAM 273->205MB).
// NEW: output stored with __stcs (evict-first) to keep L2 for X reuse.
// ---------------------------------------------------------------------------
__global__ __launch_bounds__(256, 2)
void gemm_f16_kernel(const float* __restrict__ X,
                     const float* __restrict__ bias,
                     float* __restrict__ out) {
    extern __shared__ __align__(1024) char smem[];
    const uint32_t sb = smem_u32(smem);

    const int tid  = threadIdx.x;
    const int lane = tid & 31;
    const int wid  = tid >> 5;
    const int wm   = wid & 1;        // 0..1  M (64 rows each)
    const int wn   = wid >> 1;       // 0..3  N (32 cols each)
    const int m0   = blockIdx.y * BM;   // M on slow axis
    const int n0   = blockIdx.x * BN;   // N on fast axis (siblings adjacent)
    const int h0   = (wid >> 2) & 1; // kk-half order stagger per warp group
    const int h1   = h0 ^ 1;

    // copy roles
    const int xrow  = tid >> 1;                       // 0..127
    const int xgrow = min(m0 + xrow, N_NODES - 1);    // clamp OOB rows (masked at store)
    const int hsel  = tid & 1;                        // which 16-col half of BK

    auto issue_stage = [&](int s, int k0) {
        const uint32_t st = sb + s * STG_BYTES;
        // X f32: 128 x 32 f32, 128B rows, 8 chunks, chunk' = chunk ^ (row&7)
        const float* xs = X + (size_t)xgrow * D + k0 + hsel * 16;
        const uint32_t xd = st + OFF_XF + xrow * 128;
        #pragma unroll
        for (int q = 0; q < 4; q++) {
            int ch = hsel * 4 + q;
            CP_ASYNC16(xd + ((ch ^ (xrow & 7)) << 4), xs + q * 4);
        }
        // W fp16: 128 x 32 halves, 64B rows, 4 chunks, chunk' = ch ^ ((row>>1)&3)
        const ushortT* wh = g_Wh + (size_t)(n0 + xrow) * D + k0 + hsel * 16;
        #pragma unroll
        for (int q = 0; q < 2; q++) {
            int ch = hsel * 2 + q;
            uint32_t off = (uint32_t)(xrow * 64 + ((ch ^ ((xrow >> 1) & 3)) << 4));
            CP_ASYNC16(st + OFF_BH + off, wh + q * 8);
        }
    };

    auto convert_x = [&](int s) {
        char* stc = smem + s * STG_BYTES;
        #pragma unroll
        for (int h = 0; h < 2; h++) {
            int c0 = hsel * 4 + h * 2;
            float4 f0 = *reinterpret_cast<const float4*>(
                stc + OFF_XF + xrow * 128 + ((c0 ^ (xrow & 7)) << 4));
            float4 f1 = *reinterpret_cast<const float4*>(
                stc + OFF_XF + xrow * 128 + (((c0 + 1) ^ (xrow & 7)) << 4));
            union { __half2 h2[4]; uint4 v; } ph;
            ph.h2[0] = __floats2half2_rn(f0.x, f0.y);
            ph.h2[1] = __floats2half2_rn(f0.z, f0.w);
            ph.h2[2] = __floats2half2_rn(f1.x, f1.y);
            ph.h2[3] = __floats2half2_rn(f1.z, f1.w);
            int ca = hsel * 2 + h;
            uint32_t ao = (uint32_t)(xrow * 64 + ((ca ^ ((xrow >> 1) & 3)) << 4));
            *reinterpret_cast<uint4*>(stc + OFF_AH + ao) = ph.v;
        }
    };

    float acc[4][4][4];
    #pragma unroll
    for (int i = 0; i < 4; i++)
        #pragma unroll
        for (int j = 0; j < 4; j++)
            #pragma unroll
            for (int e = 0; e < 4; e++) acc[i][j][e] = 0.0f;

    auto compute_half = [&](uint32_t stb, int kk) {
        uint32_t Af[4][4], Bh[2][4];
        #pragma unroll
        for (int i = 0; i < 4; i++) {
            int rA = wm * 64 + i * 16 + (lane & 15);
            uint32_t off = (uint32_t)(rA * 64 +
                (((kk * 2 + (lane >> 4)) ^ ((rA >> 1) & 3)) << 4));
            LDSM4(Af[i], stb + OFF_AH + off);
        }
        const int rB0 = wn * 32 + (lane & 7) + ((lane >> 4) << 3);
        #pragma unroll
        for (int jp = 0; jp < 2; jp++) {
            int rB = rB0 + jp * 16;
            uint32_t off = (uint32_t)(rB * 64 +
                (((kk * 2 + ((lane >> 3) & 1)) ^ ((rB >> 1) & 3)) << 4));
            LDSM4(Bh[jp], stb + OFF_BH + off);
        }
        #pragma unroll
        for (int i = 0; i < 4; i++)
            #pragma unroll
            for (int jp = 0; jp < 2; jp++) {
                MMA(acc[i][2 * jp],     Af[i], Bh[jp][0], Bh[jp][1]);
                MMA(acc[i][2 * jp + 1], Af[i], Bh[jp][2], Bh[jp][3]);
            }
    };

    // prologue: stages 0,1 in flight; convert 0; publish
    issue_stage(0, 0);        CP_COMMIT();
    issue_stage(1, BK);       CP_COMMIT();
    CP_WAIT1();               // stage 0 arrived (stage 1 may still fly)
    convert_x(0);
    __syncthreads();

    #pragma unroll
    for (int it = 0; it < NIT; ++it) {
        const int s = it % NSTG;
        const uint32_t stb = sb + s * STG_BYTES;

        if (it + 2 < NIT) { issue_stage((it + 2) % NSTG, (it + 2) * BK); CP_COMMIT(); }

        compute_half(stb, h0);

        if (it + 1 < NIT) {          // own-thread copy wait + private convert
            if (it + 2 < NIT) CP_WAIT1(); else CP_WAIT0();
            convert_x((it + 1) % NSTG);
        }

        compute_half(stb, h1);

        if (it + 1 < NIT) __syncthreads();   // publish stage it+1; retire stage s reads
    }

    // ---- epilogue: out[m][n] = (1+cnt[m])*acc + b[n], streaming stores ----
    float2 bj[4];
    #pragma unroll
    for (int j = 0; j < 4; j++) {
        int col = n0 + wn * 32 + j * 8 + (lane & 3) * 2;
        bj[j].x = bias[col];
        bj[j].y = bias[col + 1];
    }

    #pragma unroll
    for (int i = 0; i < 4; i++) {
        int r0 = m0 + wm * 64 + i * 16 + (lane >> 2);
        #pragma unroll
        for (int h = 0; h < 2; h++) {
            int row = r0 + h * 8;
            if (row < N_NODES) {
                float d = 1.0f + (float)g_cnt[row];
                #pragma unroll
                for (int j = 0; j < 4; j++) {
                    int col = n0 + wn * 32 + j * 8 + (lane & 3) * 2;
                    float2 o;
                    o.x = fmaf(d, acc[i][j][2 * h],     bj[j].x);
                    o.y = fmaf(d, acc[i][j][2 * h + 1], bj[j].y);
                    __stcs(reinterpret_cast<float2*>(&out[(size_t)row * D + col]), o);
                }
            }
        }
    }
}

extern "C" void kernel_launch(void* const* d_in, const int* in_sizes, int n_in,
                              void* d_out, int out_size) {
    const float* x  = (const float*)d_in[0];   // [100000, 256] f32
    const int*   ei = (const int*)d_in[1];     // [2, 3200000] i32, row 0 = src (sorted)
    const float* W  = (const float*)d_in[2];   // [256, 256] f32
    const float* b  = (const float*)d_in[3];   // [256] f32
    float* out = (float*)d_out;                // [100000, 256] f32

    prep1_kernel<<<(N_NODES + 255) / 256, 256>>>(W);      // zero cnt + convW
    prep2_kernel<<<(N_EDGES + 255) / 256, 256>>>(ei);     // aggregated atomics

    cudaFuncSetAttribute(gemm_f16_kernel,
                         cudaFuncAttributeMaxDynamicSharedMemorySize, SMEM_TOTAL);
    dim3 grid(D / BN, (N_NODES + BM - 1) / BM);           // (2, 782): N fast axis
    gemm_f16_kernel<<<grid, 256, SMEM_TOTAL>>>(x, b, out);
}